// round 2
// baseline (speedup 1.0000x reference)
#include <cuda_runtime.h>

// Problem constants
#define NB   8
#define CIN  2
#define HIN  128
#define WIN  128
#define TT   32
#define CHO  32
#define HP   64
#define WP   64
#define WPT  16          // wp columns per block
#define NTHR 256         // 8 warps; each warp covers 2 wp, each lane covers 2 ch

// packed f32x2 fma: d = a*b + d (two fp32 lanes per instruction)
__device__ __forceinline__ void fma2(unsigned long long &d,
                                     unsigned long long a,
                                     unsigned long long b) {
    asm("fma.rn.f32x2 %0, %1, %2, %3;" : "=l"(d) : "l"(a), "l"(b), "l"(d));
}

__global__ __launch_bounds__(NTHR, 4)
void snn_encoder_kernel(const float* __restrict__ spike,
                        const float* __restrict__ weight_v,
                        const float* __restrict__ weight_g,
                        const float* __restrict__ delay,
                        float* __restrict__ out) {
    // input tile: [c(2)][r(3)][w(33)][t(32)] floats
    __shared__ __align__(16) float sin_[CIN * 3 * 33 * TT];              // 25344 B
    // normalized weights, f32x2-duplicated, channel-pair packed:
    // swt2[tap][c2] = { dup(w[c2]), dup(w[c2+16]) }  -> one LDS.128 per tap
    __shared__ __align__(16) unsigned long long swt2[18 * 16 * 2];        // 4608 B

    const int tid  = threadIdx.x;
    const int w    = tid >> 5;        // warp 0..7
    const int lane = tid & 31;
    const int c2   = lane & 15;       // channel pair base: channels c2 and c2+16
    const int wsub = lane >> 4;       // which wp of the warp's two
    const int wp_l = w + 8 * wsub;    // 0..15
    const int wp0  = blockIdx.x * WPT;
    const int hp   = blockIdx.y;
    const int n    = blockIdx.z;

    // ---- weight norm (one thread per output channel) ----
    if (tid < 32) {
        float wv[18];
        float ss = 0.f;
        #pragma unroll
        for (int k = 0; k < 18; k++) {
            wv[k] = weight_v[tid * 18 + k];
            ss += wv[k] * wv[k];
        }
        const float sc = weight_g[tid] / sqrtf(ss);
        const int col = tid & 15, half = tid >> 4;
        #pragma unroll
        for (int k = 0; k < 18; k++) {
            const unsigned int wu = __float_as_uint(wv[k] * sc);
            swt2[(k * 16 + col) * 2 + half] = ((unsigned long long)wu << 32) | wu;
        }
    }

    // ---- cooperative input tile load (fully coalesced; (w,t) contiguous) ----
    const int h0 = 2 * hp - 1;
    const int w0 = 2 * wp0 - 1;
    for (int idx = tid; idx < 6 * 33 * 8; idx += NTHR) {
        const int plane = idx / (33 * 8);          // c*3 + r
        const int rem   = idx - plane * (33 * 8);
        const int wj    = rem >> 3;
        const int t4    = rem & 7;
        const int c = plane / 3;
        const int r = plane - c * 3;
        const int h = h0 + r;
        const int ww = w0 + wj;
        float4 v = make_float4(0.f, 0.f, 0.f, 0.f);
        if ((unsigned)h < HIN && (unsigned)ww < WIN) {
            v = *(const float4*)(spike +
                (((size_t)(n * CIN + c) * HIN + h) * WIN + ww) * TT + t4 * 4);
        }
        *(float4*)(sin_ + (plane * 33 + wj) * TT + t4 * 4) = v;
    }
    __syncthreads();

    // ---- conv (f32x2, 2 channels per thread share tap loads) + LIF scan ----
    float cur0 = 0.f, volt0 = 0.f;
    float cur1 = 0.f, volt1 = 0.f;
    unsigned int bits0 = 0u, bits1 = 0u;

    const float* tapbase = sin_ + 2 * wp_l * TT;

    #pragma unroll
    for (int chunk = 0; chunk < 4; chunk++) {
        unsigned long long za[4] = {0ull, 0ull, 0ull, 0ull};
        unsigned long long zb[4] = {0ull, 0ull, 0ull, 0ull};
        #pragma unroll
        for (int c = 0; c < CIN; c++) {
            #pragma unroll
            for (int r = 0; r < 3; r++) {
                #pragma unroll
                for (int kw = 0; kw < 3; kw++) {
                    const int k = c * 9 + r * 3 + kw;
                    const ulonglong2* x = (const ulonglong2*)(
                        tapbase + ((c * 3 + r) * 33 + kw) * TT + chunk * 8);
                    const ulonglong2 w2 = *(const ulonglong2*)&swt2[(k * 16 + c2) * 2];
                    const ulonglong2 a = x[0];
                    const ulonglong2 b = x[1];
                    fma2(za[0], a.x, w2.x);
                    fma2(zb[0], a.x, w2.y);
                    fma2(za[1], a.y, w2.x);
                    fma2(zb[1], a.y, w2.y);
                    fma2(za[2], b.x, w2.x);
                    fma2(zb[2], b.x, w2.y);
                    fma2(za[3], b.y, w2.x);
                    fma2(zb[3], b.y, w2.y);
                }
            }
        }
        // LIF over 8 timesteps of this chunk, both channels (independent -> ILP)
        #pragma unroll
        for (int j = 0; j < 4; j++) {
            const int t = chunk * 8 + j * 2;
            const float za_l = __uint_as_float((unsigned)(za[j] & 0xffffffffull));
            const float za_h = __uint_as_float((unsigned)(za[j] >> 32));
            const float zb_l = __uint_as_float((unsigned)(zb[j] & 0xffffffffull));
            const float zb_h = __uint_as_float((unsigned)(zb[j] >> 32));

            cur0  = cur0 * 0.75f + za_l;
            cur1  = cur1 * 0.75f + zb_l;
            volt0 = volt0 * 0.9f + cur0;
            volt1 = volt1 * 0.9f + cur1;
            if (volt0 >= 1.0f) { bits0 |= 1u << t; volt0 = 0.f; }
            if (volt1 >= 1.0f) { bits1 |= 1u << t; volt1 = 0.f; }

            cur0  = cur0 * 0.75f + za_h;
            cur1  = cur1 * 0.75f + zb_h;
            volt0 = volt0 * 0.9f + cur0;
            volt1 = volt1 * 0.9f + cur1;
            if (volt0 >= 1.0f) { bits0 |= 1u << (t + 1); volt0 = 0.f; }
            if (volt1 >= 1.0f) { bits1 |= 1u << (t + 1); volt1 = 0.f; }
        }
    }

    // ---- per-channel fractional delay + output write (both channels) ----
    #pragma unroll
    for (int half = 0; half < 2; half++) {
        const int ch = c2 + 16 * half;
        const unsigned int bits = half ? bits1 : bits0;
        const float d  = delay[ch];
        const int   di = (int)floorf(d);
        const float f  = d - (float)di;
        unsigned int b0 = 0u, b1 = 0u;
        if (di >= 0 && di < 32)         b0 = bits << di;
        if (di + 1 >= 0 && di + 1 < 32) b1 = bits << (di + 1);
        const float onef = 1.0f - f;

        float* op = out + (((size_t)((n * CHO + ch) * HP + hp) * WP + (wp0 + wp_l)) * TT);
        #pragma unroll
        for (int t4 = 0; t4 < 8; t4++) {
            const int t = t4 * 4;
            float4 v;
            v.x = onef * (float)((b0 >> (t + 0)) & 1u) + f * (float)((b1 >> (t + 0)) & 1u);
            v.y = onef * (float)((b0 >> (t + 1)) & 1u) + f * (float)((b1 >> (t + 1)) & 1u);
            v.z = onef * (float)((b0 >> (t + 2)) & 1u) + f * (float)((b1 >> (t + 2)) & 1u);
            v.w = onef * (float)((b0 >> (t + 3)) & 1u) + f * (float)((b1 >> (t + 3)) & 1u);
            *(float4*)(op + t) = v;
        }
    }
}

extern "C" void kernel_launch(void* const* d_in, const int* in_sizes, int n_in,
                              void* d_out, int out_size) {
    const float* spike    = (const float*)d_in[0];
    const float* weight_v = (const float*)d_in[1];
    const float* weight_g = (const float*)d_in[2];
    const float* delay    = (const float*)d_in[3];
    float* out = (float*)d_out;

    dim3 grid(WP / WPT, HP, NB);   // (4, 64, 8) = 2048 blocks
    snn_encoder_kernel<<<grid, NTHR>>>(spike, weight_v, weight_g, delay, out);
}

// round 3
// speedup vs baseline: 1.7521x; 1.7521x over previous
#include <cuda_runtime.h>

// Problem constants
#define NB   8
#define CIN  2
#define HIN  128
#define WIN  128
#define TT   32
#define CHO  32
#define HP   64
#define WP   64
#define WPT  16          // wp columns per block
#define NTHR 512         // 16 warps: warp = wp column, lane = channel

// packed f32x2 fma: d = a*b + d (two fp32 lanes per instruction)
__device__ __forceinline__ void fma2(unsigned long long &d,
                                     unsigned long long a,
                                     unsigned long long b) {
    asm("fma.rn.f32x2 %0, %1, %2, %3;" : "=l"(d) : "l"(a), "l"(b), "l"(d));
}

__global__ __launch_bounds__(NTHR, 2)
void snn_encoder_kernel(const float* __restrict__ spike,
                        const float* __restrict__ weight_v,
                        const float* __restrict__ weight_g,
                        const float* __restrict__ delay,
                        float* __restrict__ out) {
    // input tile: [c(2)][r(3)][w(33)][t(32)] floats
    __shared__ __align__(16) float sin_[CIN * 3 * 33 * TT];            // 25344 B
    // normalized weights, duplicated into both f32x2 halves: [tap(18)][ch(32)]
    __shared__ __align__(16) unsigned long long swt[18 * CHO];          // 4608 B
    // spike bitmasks for transposed coalesced epilogue: [ch(32)][wp(16)]
    __shared__ unsigned int sbits[CHO][WPT];                            // 2048 B

    const int tid  = threadIdx.x;
    const int ch   = tid & 31;       // lane = channel  -> smem tap reads broadcast
    const int wp_l = tid >> 5;       // warp = wp column (0..15)
    const int wp0  = blockIdx.x * WPT;
    const int hp   = blockIdx.y;
    const int n    = blockIdx.z;

    // ---- weight norm (warp 0: one thread per output channel) ----
    if (tid < 32) {
        float wv[18];
        float ss = 0.f;
        #pragma unroll
        for (int k = 0; k < 18; k++) {
            wv[k] = weight_v[tid * 18 + k];
            ss += wv[k] * wv[k];
        }
        const float sc = weight_g[tid] / sqrtf(ss);
        #pragma unroll
        for (int k = 0; k < 18; k++) {
            const unsigned int wu = __float_as_uint(wv[k] * sc);
            swt[k * 32 + tid] = ((unsigned long long)wu << 32) | wu;
        }
    }

    // ---- cooperative input tile load (fully coalesced; (w,t) is contiguous) ----
    const int h0 = 2 * hp - 1;
    const int w0 = 2 * wp0 - 1;
    for (int idx = tid; idx < 6 * 33 * 8; idx += NTHR) {
        const int plane = idx / (33 * 8);          // c*3 + r
        const int rem   = idx - plane * (33 * 8);
        const int wj    = rem >> 3;
        const int t4    = rem & 7;
        const int c = plane / 3;
        const int r = plane - c * 3;
        const int h = h0 + r;
        const int w = w0 + wj;
        float4 v = make_float4(0.f, 0.f, 0.f, 0.f);
        if ((unsigned)h < HIN && (unsigned)w < WIN) {
            v = *(const float4*)(spike +
                (((size_t)(n * CIN + c) * HIN + h) * WIN + w) * TT + t4 * 4);
        }
        *(float4*)(sin_ + (plane * 33 + wj) * TT + t4 * 4) = v;
    }
    __syncthreads();

    // ---- conv (f32x2, broadcast taps) + LIF scan, t in 4 chunks of 8 ----
    float cur = 0.f, volt = 0.f;
    unsigned int bits = 0u;

    #pragma unroll
    for (int chunk = 0; chunk < 4; chunk++) {
        unsigned long long z2[4] = {0ull, 0ull, 0ull, 0ull};
        #pragma unroll
        for (int c = 0; c < CIN; c++) {
            #pragma unroll
            for (int r = 0; r < 3; r++) {
                #pragma unroll
                for (int kw = 0; kw < 3; kw++) {
                    const int wloc = 2 * wp_l + kw;               // 0..32
                    const ulonglong2* x = (const ulonglong2*)(
                        sin_ + ((c * 3 + r) * 33 + wloc) * TT + chunk * 8);
                    const unsigned long long w2 = swt[(c * 9 + r * 3 + kw) * 32 + ch];
                    const ulonglong2 a = x[0];
                    const ulonglong2 b = x[1];
                    fma2(z2[0], a.x, w2);
                    fma2(z2[1], a.y, w2);
                    fma2(z2[2], b.x, w2);
                    fma2(z2[3], b.y, w2);
                }
            }
        }
        // LIF over 8 timesteps of this chunk
        #pragma unroll
        for (int j = 0; j < 4; j++) {
            const float zl = __uint_as_float((unsigned)(z2[j] & 0xffffffffull));
            const float zh = __uint_as_float((unsigned)(z2[j] >> 32));
            const int t = chunk * 8 + j * 2;
            cur  = cur * 0.75f + zl;
            volt = volt * 0.9f + cur;
            if (volt >= 1.0f) { bits |= 1u << t; volt = 0.f; }
            cur  = cur * 0.75f + zh;
            volt = volt * 0.9f + cur;
            if (volt >= 1.0f) { bits |= 1u << (t + 1); volt = 0.f; }
        }
    }

    // ---- transpose spike masks through smem for a coalesced epilogue ----
    sbits[ch][wp_l] = bits;
    __syncthreads();

    // warp wp_l writes channels wp_l and wp_l+16; each channel is a contiguous
    // 2 KB run (16 wp x 32 t floats) -> every STG.128 is 512 B fully coalesced.
    const int lane = ch;  // alias for clarity in epilogue role
    #pragma unroll
    for (int half = 0; half < 2; half++) {
        const int och = wp_l + 16 * half;
        const float d  = delay[och];                 // uniform per warp
        const int   di = (int)floorf(d);
        const float f  = d - (float)di;
        const float onef = 1.0f - f;
        float* obase = out +
            (((size_t)((n * CHO + och) * HP + hp) * WP + wp0) * TT);
        #pragma unroll
        for (int i = 0; i < 4; i++) {
            const int idx = i * 32 + lane;           // 0..127 float4 slots
            const int wpi = idx >> 3;                // 0..15
            const int t   = (idx & 7) * 4;           // 0..28
            const unsigned int bt = sbits[och][wpi];
            unsigned int b0 = 0u, b1 = 0u;
            if (di >= 0 && di < 32)         b0 = bt << di;
            if (di + 1 >= 0 && di + 1 < 32) b1 = bt << (di + 1);
            float4 v;
            v.x = onef * (float)((b0 >> (t + 0)) & 1u) + f * (float)((b1 >> (t + 0)) & 1u);
            v.y = onef * (float)((b0 >> (t + 1)) & 1u) + f * (float)((b1 >> (t + 1)) & 1u);
            v.z = onef * (float)((b0 >> (t + 2)) & 1u) + f * (float)((b1 >> (t + 2)) & 1u);
            v.w = onef * (float)((b0 >> (t + 3)) & 1u) + f * (float)((b1 >> (t + 3)) & 1u);
            *(float4*)(obase + idx * 4) = v;
        }
    }
}

extern "C" void kernel_launch(void* const* d_in, const int* in_sizes, int n_in,
                              void* d_out, int out_size) {
    const float* spike    = (const float*)d_in[0];
    const float* weight_v = (const float*)d_in[1];
    const float* weight_g = (const float*)d_in[2];
    const float* delay    = (const float*)d_in[3];
    float* out = (float*)d_out;

    dim3 grid(WP / WPT, HP, NB);   // (4, 64, 8) = 2048 blocks
    snn_encoder_kernel<<<grid, NTHR>>>(spike, weight_v, weight_g, delay, out);
}